// round 5
// baseline (speedup 1.0000x reference)
#include <cuda_runtime.h>
#include <cstdint>

// ---------------------------------------------------------------------------
// Compile-time G(3,0,1) blade algebra (verified: rel_err 8.5e-8).
// Basis order: 0:1 1:e0 2:e1 3:e2 4:e3 5:e01 6:e02 7:e03 8:e12 9:e13 10:e23
//              11:e012 12:e013 13:e023 14:e123 15:e0123
// ---------------------------------------------------------------------------

namespace ga {

__host__ __device__ constexpr int mask_of(int i) {
    const int t[16] = {0, 1, 2, 4, 8, 3, 5, 9, 6, 10, 12, 7, 11, 13, 14, 15};
    return t[i];
}
__host__ __device__ constexpr int idx_of(int m) {
    const int t[16] = {0, 1, 2, 5, 3, 6, 8, 11, 4, 7, 9, 12, 10, 13, 14, 15};
    return t[m];
}
__host__ __device__ constexpr int popc4(int m) {
    return (m & 1) + ((m >> 1) & 1) + ((m >> 2) & 1) + ((m >> 3) & 1);
}
__host__ __device__ constexpr int rsign(int a, int b) {
    int cnt = 0;
    for (int i = 1; i < 4; ++i)
        if ((a >> i) & 1) cnt += popc4(b & ((1 << i) - 1));
    return (cnt & 1) ? -1 : 1;
}

__host__ __device__ constexpr int gp_coef(int k, int j) {
    const int mk = mask_of(k), mj = mask_of(j);
    const int mi = mk ^ mj;
    if (mi & mj & 1) return 0;              // shared e0 -> metric 0
    return rsign(mi, mj);
}
__host__ __device__ constexpr int gp_src(int k, int j) {
    return idx_of(mask_of(k) ^ mask_of(j));
}

__host__ __device__ constexpr int jn_coef(int k, int j) {
    const int mk = mask_of(k), mj = mask_of(j);
    const int nmj = ~mj & 15;
    if (mk & nmj) return 0;                 // requires mk subset of mj
    const int mi = mk | nmj;
    return rsign(~mk & 15, mk)
         * rsign(mi, ~mi & 15)
         * rsign(mj, ~mj & 15)
         * rsign(~mi & 15, nmj);
}
__host__ __device__ constexpr int jn_src(int k, int j) {
    const int mk = mask_of(k), mj = mask_of(j);
    return idx_of(mk | (~mj & 15));
}

template <int K, int J>
__device__ __forceinline__ float gp_term(const float (&x)[16], const float (&y)[16]) {
    if constexpr (J >= 16) {
        return 0.0f;
    } else {
        float acc = gp_term<K, J + 1>(x, y);
        constexpr int c = gp_coef(K, J);
        constexpr int p = gp_src(K, J);
        if constexpr (c == 1)  acc = fmaf(x[p], y[J], acc);
        if constexpr (c == -1) acc = fmaf(-x[p], y[J], acc);
        return acc;
    }
}

template <int K, int J>
__device__ __forceinline__ float jn_term(const float (&x)[16], const float (&y)[16]) {
    if constexpr (J >= 16) {
        return 0.0f;
    } else {
        float acc = jn_term<K, J + 1>(x, y);
        constexpr int c = jn_coef(K, J);
        constexpr int p = jn_src(K, J);
        if constexpr (c == 1)  acc = fmaf(x[p], y[J], acc);
        if constexpr (c == -1) acc = fmaf(-x[p], y[J], acc);
        return acc;
    }
}

template <int K>
__device__ __forceinline__ float4 gp_quad(const float (&x)[16], const float (&y)[16]) {
    return make_float4(gp_term<K + 0, 0>(x, y), gp_term<K + 1, 0>(x, y),
                       gp_term<K + 2, 0>(x, y), gp_term<K + 3, 0>(x, y));
}

template <int K>
__device__ __forceinline__ float4 jn_quad(const float (&x)[16], const float (&y)[16],
                                          float r15) {
    return make_float4(r15 * jn_term<K + 0, 0>(x, y), r15 * jn_term<K + 1, 0>(x, y),
                       r15 * jn_term<K + 2, 0>(x, y), r15 * jn_term<K + 3, 0>(x, y));
}

}  // namespace ga

// ---------------------------------------------------------------------------
// cp.async (LDGSTS) warp-private double-buffered streaming pipeline.
// MLP lives in smem, not registers: each warp keeps its entire next stage
// (32 points x 132B) in flight while computing the current one.
// ---------------------------------------------------------------------------

constexpr int TPB  = 128;   // 4 warps per CTA
constexpr int WARPS = TPB / 32;
constexpr int PPT  = 128;   // points per tile (CTA)
constexpr int PPW  = 32;    // points per warp per stage
// smem per warp-stage: 8 chunks (x0..3, y0..3) * 32 points * 16B + 32 * 4B ref
constexpr int DATA_BYTES  = 8 * PPW * 16;          // 4096
constexpr int STAGE_BYTES = DATA_BYTES + PPW * 4;  // 4224
constexpr int WARP_SMEM   = 2 * STAGE_BYTES;       // 8448 (double buffer)

__device__ __forceinline__ void cp16(uint32_t dst, const void* src) {
    asm volatile("cp.async.cg.shared.global [%0], [%1], 16;\n" :: "r"(dst), "l"(src));
}
__device__ __forceinline__ void cp4(uint32_t dst, const void* src) {
    asm volatile("cp.async.ca.shared.global [%0], [%1], 4;\n" :: "r"(dst), "l"(src));
}
__device__ __forceinline__ void cp_commit() {
    asm volatile("cp.async.commit_group;\n" ::: "memory");
}
template <int N>
__device__ __forceinline__ void cp_wait() {
    asm volatile("cp.async.wait_group %0;\n" :: "n"(N) : "memory");
}

// Issue this warp's async loads for one stage. P0 = warp's first global point,
// cnt = number of valid points (<=32). Fully coalesced: each cp16 op's 32
// lanes cover a contiguous 512B span of gmem.
__device__ __forceinline__ void load_stage(const char* __restrict__ xg,
                                           const char* __restrict__ yg,
                                           const char* __restrict__ refg,
                                           int P0, int cnt,
                                           uint32_t sbase, int lane) {
    const char* xs = xg + (size_t)P0 * 64;
    const char* ys = yg + (size_t)P0 * 64;
    const int c  = lane & 3;        // chunk within point
    const int pb = lane >> 2;       // point sub-index (0..7)
#pragma unroll
    for (int i = 0; i < 4; ++i) {
        const int p = pb + 8 * i;   // local point 0..31
        if (p < cnt) {
            // smem chunk-major: chunk*512 + point*16 (conflict-free LDS.128)
            cp16(sbase + c * 512 + p * 16,        xs + p * 64 + c * 16);
            cp16(sbase + (4 + c) * 512 + p * 16,  ys + p * 64 + c * 16);
        }
    }
    if (lane < cnt)
        cp4(sbase + DATA_BYTES + lane * 4,
            refg + (size_t)(P0 + lane) * 64 + 60);   // ref[point][15]
}

__device__ __forceinline__ void compute_store(const char* __restrict__ sb, int lane,
                                              int gp, float4* __restrict__ o4) {
    float x[16], y[16];
#pragma unroll
    for (int c = 0; c < 4; ++c) {
        const float4 vx = *(const float4*)(sb + c * 512 + lane * 16);
        const float4 vy = *(const float4*)(sb + (4 + c) * 512 + lane * 16);
        x[4*c+0]=vx.x; x[4*c+1]=vx.y; x[4*c+2]=vx.z; x[4*c+3]=vx.w;
        y[4*c+0]=vy.x; y[4*c+1]=vy.y; y[4*c+2]=vy.z; y[4*c+3]=vy.w;
    }
    const float r15 = *(const float*)(sb + DATA_BYTES + lane * 4);

    float4* outp = o4 + (size_t)gp * 8;
    __stcs(outp + 0, ga::gp_quad<0>(x, y));
    __stcs(outp + 1, ga::gp_quad<4>(x, y));
    __stcs(outp + 2, ga::gp_quad<8>(x, y));
    __stcs(outp + 3, ga::gp_quad<12>(x, y));
    __stcs(outp + 4, ga::jn_quad<0>(x, y, r15));
    __stcs(outp + 5, ga::jn_quad<4>(x, y, r15));
    __stcs(outp + 6, ga::jn_quad<8>(x, y, r15));
    __stcs(outp + 7, ga::jn_quad<12>(x, y, r15));
}

__global__ __launch_bounds__(TPB, 6)
void MVGeometricBilinear_kernel(const float* __restrict__ xg,
                                const float* __restrict__ yg,
                                const float* __restrict__ refg,
                                float4* __restrict__ o4,
                                int npts) {
    __shared__ __align__(16) char smem[WARPS * WARP_SMEM];   // 33792 B

    const int lane = threadIdx.x & 31;
    const int w    = threadIdx.x >> 5;
    const int ntiles = (npts + PPT - 1) / PPT;
    const int stride = gridDim.x;

    int tile = blockIdx.x;
    if (tile >= ntiles) return;

    char* wb = smem + w * WARP_SMEM;
    const uint32_t wb_s = (uint32_t)__cvta_generic_to_shared(wb);

    auto p0_of  = [&](int t) { return t * PPT + w * PPW; };
    auto cnt_of = [&](int t) {
        int rem = npts - (t * PPT + w * PPW);
        return rem < 0 ? 0 : (rem > PPW ? PPW : rem);
    };

    // prologue: stage 0
    load_stage((const char*)xg, (const char*)yg, (const char*)refg,
               p0_of(tile), cnt_of(tile), wb_s, lane);
    cp_commit();

    int s = 0;
    while (true) {
        const int nxt = tile + stride;
        if (nxt < ntiles) {
            load_stage((const char*)xg, (const char*)yg, (const char*)refg,
                       p0_of(nxt), cnt_of(nxt),
                       wb_s + (s ^ 1) * STAGE_BYTES, lane);
            cp_commit();
            cp_wait<1>();        // current stage complete
        } else {
            cp_wait<0>();
        }
        __syncwarp();            // cross-lane visibility of smem fills

        const int cnt = cnt_of(tile);
        if (lane < cnt)
            compute_store(wb + s * STAGE_BYTES, lane, p0_of(tile) + lane, o4);

        if (nxt >= ntiles) break;
        __syncwarp();            // all lanes done reading before buffer reuse
        tile = nxt;
        s ^= 1;
    }
}

extern "C" void kernel_launch(void* const* d_in, const int* in_sizes, int n_in,
                              void* d_out, int out_size) {
    const float* x   = (const float*)d_in[0];
    const float* y   = (const float*)d_in[1];
    const float* ref = (const float*)d_in[2];
    float* out       = (float*)d_out;

    const int npts = in_sizes[0] / 16;
    const int ntiles = (npts + PPT - 1) / PPT;
    int blocks = 148 * 6;                 // persistent: 6 CTAs/SM (smem-limited)
    if (blocks > ntiles) blocks = ntiles;

    MVGeometricBilinear_kernel<<<blocks, TPB>>>(x, y, ref, (float4*)out, npts);
}